// round 7
// baseline (speedup 1.0000x reference)
#include <cuda_runtime.h>
#include <math.h>

#define NATOM 32768
#define KNBR 16
#define NEDGE (NATOM*KNBR)

typedef unsigned long long u64;

__device__ __forceinline__ u64 pack2(float a, float b) {
    u64 r; asm("mov.b64 %0, {%1,%2};" : "=l"(r) : "f"(a), "f"(b)); return r;
}
__device__ __forceinline__ void unpack2(u64 v, float& a, float& b) {
    asm("mov.b64 {%0,%1}, %2;" : "=f"(a), "=f"(b) : "l"(v));
}
__device__ __forceinline__ u64 ffma2(u64 a, u64 b, u64 c) {
    u64 d; asm("fma.rn.f32x2 %0, %1, %2, %3;" : "=l"(d) : "l"(a), "l"(b), "l"(c)); return d;
}

__device__ __align__(16) float g_basisT[(size_t)10*NEDGE];   // [b][e]
__device__ __align__(16) float g_Y[(size_t)NEDGE*16];
__device__ __align__(16) float g_wT[(size_t)256*NEDGE];      // [j][e] per layer
__device__ __align__(16) float g_featA[(size_t)NATOM*64];
__device__ __align__(16) float g_featB[(size_t)NATOM*64];
__device__ float g_part[64*64];

__global__ void geom_kernel(const float* __restrict__ coords,
                            const float* __restrict__ shift,
                            const int*   __restrict__ nbr)
{
    int e = blockIdx.x*blockDim.x + threadIdx.x;
    if (e >= NEDGE) return;
    int n  = e >> 4;
    int nb = nbr[e];
    float x = coords[3*nb+0] + shift[3*(size_t)e+0] - coords[3*n+0];
    float y = coords[3*nb+1] + shift[3*(size_t)e+1] - coords[3*n+1];
    float z = coords[3*nb+2] + shift[3*(size_t)e+2] - coords[3*n+2];
    float r  = sqrtf(x*x + y*y + z*z);
    float inv = 1.0f/fmaxf(r, 1e-6f);
    float dx = x*inv, dy = y*inv, dz = z*inv;
    float x2 = dx*dx, y2 = dy*dy, z2 = dz*dz;
    float Y[16];
    Y[0]=0.4886025f*dy; Y[1]=0.4886025f*dz; Y[2]=0.4886025f*dx;
    Y[3]=1.0925484f*dx*dy; Y[4]=1.0925484f*dy*dz; Y[5]=0.3153916f*(3.f*z2-1.f);
    Y[6]=1.0925484f*dx*dz; Y[7]=0.5462742f*(x2-y2);
    Y[8]=0.5900436f*dy*(3.f*x2-y2); Y[9]=2.8906114f*dx*dy*dz;
    Y[10]=0.4570458f*dy*(5.f*z2-1.f); Y[11]=0.3731763f*dz*(5.f*z2-3.f);
    Y[12]=0.4570458f*dx*(5.f*z2-1.f); Y[13]=1.4453057f*(x2-y2)*dz;
    Y[14]=0.5900436f*dx*(x2-3.f*y2); Y[15]=0.f;
    float* Yp = g_Y + (size_t)e*16;
#pragma unroll
    for (int q=0;q<4;q++)
        *(float4*)(Yp+4*q) = make_float4(Y[4*q],Y[4*q+1],Y[4*q+2],Y[4*q+3]);
    float mask = (r < 2.0f && r > 1e-6f) ? 1.f : 0.f;
    const float step = 2.0f/9.0f, invstep = 4.5f;
#pragma unroll
    for (int b=0;b<10;b++) {
        float xr = (r - (float)b*step)*invstep;
        float v = 0.f;
        if (fabsf(xr) < 1.0f) { float c = cospif(0.5f*xr); v = c*c; }
        g_basisT[(size_t)b*NEDGE + e] = v*mask;
    }
}

// smem (floats): s_w1[1000] | s_wB[max(10000, NW*100)] | s_h1[100*128] | s_h2[100*128]
template<int NW> struct RK {
    static constexpr int WBF  = (NW*100 > 10000) ? NW*100 : 10000;
    static constexpr int OFF_H1 = 1000 + WBF;
    static constexpr int OFF_H2 = OFF_H1 + 12800;
    static constexpr int SMEMB  = (OFF_H2 + 12800) * 4;
    static constexpr int JPW    = (NW + 15) / 16;   // 2, 10, 16 (all even)
    static constexpr int JP2    = JPW / 2;          // 1, 5, 8
};

template<int NW>
__global__ void __launch_bounds__(512) radial_kernel(
    const float* __restrict__ W1, const float* __restrict__ W2,
    const float* __restrict__ W3)
{
    extern __shared__ float sm[];
    float* s_w1 = sm;                       // [10][100]
    float* s_wB = sm + 1000;                // W2 [k][100] then W3 [k][NW]
    float* s_h1 = sm + RK<NW>::OFF_H1;      // [k][e] 100x128
    float* s_h2 = sm + RK<NW>::OFF_H2;      // [j][e] 100x128 (head reused for basisT)
    float* s_bT = s_h2;                     // [b][e] 10x128
    const int tid  = threadIdx.x;
    const int e0   = (tid & 31) * 4;        // lanes span edges -> conflict-free LDS.128
    const int warp = tid >> 5;
    const size_t ebase = (size_t)blockIdx.x*128;

    for (int i = tid; i < 1000; i += 512) s_w1[i] = W1[i];
    for (int i = tid; i < 1280; i += 512) {
        int b = i >> 7, e = i & 127;
        s_bT[b*128 + e] = g_basisT[(size_t)b*NEDGE + ebase + e];
    }
    for (int i = tid; i < 10000; i += 512) s_wB[i] = W2[i];
    __syncthreads();

    // phase A: h1[k][e] = relu(basis @ W1), f32x2 packed along e
    for (int iq = tid; iq < 3200; iq += 512) {
        int k = iq >> 5, c0 = (iq & 31) * 4;
        u64 a01 = 0ull, a23 = 0ull;
#pragma unroll
        for (int b = 0; b < 10; b++) {
            const u64* bv = (const u64*)&s_bT[b*128 + c0];
            u64 wd = pack2(s_w1[b*100 + k], s_w1[b*100 + k]);
            a01 = ffma2(bv[0], wd, a01);
            a23 = ffma2(bv[1], wd, a23);
        }
        float r0,r1,r2,r3;
        unpack2(a01, r0, r1); unpack2(a23, r2, r3);
        *(float4*)&s_h1[k*128 + c0] =
            make_float4(fmaxf(r0,0.f), fmaxf(r1,0.f), fmaxf(r2,0.f), fmaxf(r3,0.f));
    }
    __syncthreads();

    // phase B: h2[j][e] = relu(W2 @ h1); warps 0..11 -> 8 j, warp 12 -> 4 j
    {
        const int jbeg = warp*8;
        if (jbeg < 100) {
            const int np = ((100 - jbeg < 8) ? (100 - jbeg) : 8) / 2;  // pairs
            u64 acc2[4][4];
#pragma unroll
            for (int jp=0;jp<4;jp++)
#pragma unroll
                for (int ee=0;ee<4;ee++) acc2[jp][ee] = 0ull;
#pragma unroll 2
            for (int k = 0; k < 100; k++) {
                float4 h = *(const float4*)&s_h1[k*128 + e0];
                u64 hd[4] = {pack2(h.x,h.x), pack2(h.y,h.y),
                             pack2(h.z,h.z), pack2(h.w,h.w)};
                const u64* wr = (const u64*)&s_wB[k*100 + jbeg];
#pragma unroll
                for (int jp=0;jp<4;jp++)
                    if (jp < np) {
                        u64 w = wr[jp];
#pragma unroll
                        for (int ee=0;ee<4;ee++)
                            acc2[jp][ee] = ffma2(hd[ee], w, acc2[jp][ee]);
                    }
            }
#pragma unroll
            for (int jp=0;jp<4;jp++)
                if (jp < np) {
                    float lo[4], hi[4];
#pragma unroll
                    for (int ee=0;ee<4;ee++) unpack2(acc2[jp][ee], lo[ee], hi[ee]);
                    *(float4*)&s_h2[(jbeg+2*jp)*128 + e0] =
                        make_float4(fmaxf(lo[0],0.f),fmaxf(lo[1],0.f),
                                    fmaxf(lo[2],0.f),fmaxf(lo[3],0.f));
                    *(float4*)&s_h2[(jbeg+2*jp+1)*128 + e0] =
                        make_float4(fmaxf(hi[0],0.f),fmaxf(hi[1],0.f),
                                    fmaxf(hi[2],0.f),fmaxf(hi[3],0.f));
                }
        }
    }
    __syncthreads();
    for (int i = tid; i < 100*NW; i += 512) s_wB[i] = W3[i];
    __syncthreads();

    // phase C: out[j][e] = h2 @ W3; JPW j per warp, f32x2 j-pairs
    {
        constexpr int JP2 = RK<NW>::JP2;
        const int jbeg = warp*RK<NW>::JPW;
        if (jbeg < NW) {
            const int np = ((NW - jbeg < RK<NW>::JPW) ? (NW - jbeg) : RK<NW>::JPW) / 2;
            u64 acc2[JP2][4];
#pragma unroll
            for (int jp=0;jp<JP2;jp++)
#pragma unroll
                for (int ee=0;ee<4;ee++) acc2[jp][ee] = 0ull;
#pragma unroll 2
            for (int k = 0; k < 100; k++) {
                float4 h = *(const float4*)&s_h2[k*128 + e0];
                u64 hd[4] = {pack2(h.x,h.x), pack2(h.y,h.y),
                             pack2(h.z,h.z), pack2(h.w,h.w)};
                const u64* wr = (const u64*)&s_wB[k*NW + jbeg];
#pragma unroll
                for (int jp=0;jp<JP2;jp++)
                    if (jp < np) {
                        u64 w = wr[jp];
#pragma unroll
                        for (int ee=0;ee<4;ee++)
                            acc2[jp][ee] = ffma2(hd[ee], w, acc2[jp][ee]);
                    }
            }
#pragma unroll
            for (int jp=0;jp<JP2;jp++)
                if (jp < np) {
                    float lo[4], hi[4];
#pragma unroll
                    for (int ee=0;ee<4;ee++) unpack2(acc2[jp][ee], lo[ee], hi[ee]);
                    *(float4*)&g_wT[(size_t)(jbeg+2*jp)*NEDGE + ebase + e0] =
                        make_float4(lo[0],lo[1],lo[2],lo[3]);
                    *(float4*)&g_wT[(size_t)(jbeg+2*jp+1)*NEDGE + ebase + e0] =
                        make_float4(hi[0],hi[1],hi[2],hi[3]);
                }
        }
    }
}

__device__ __forceinline__ float red16(float v) {
    v += __shfl_xor_sync(0xffffffffu, v, 8);
    v += __shfl_xor_sync(0xffffffffu, v, 4);
    v += __shfl_xor_sync(0xffffffffu, v, 2);
    v += __shfl_xor_sync(0xffffffffu, v, 1);
    return v;
}
__constant__ int c_ML[3] = {3,5,7};
__constant__ int c_AO[3] = {0,12,32};
__constant__ int c_YO[3] = {0,3,8};
__constant__ int c_FO[3] = {4,16,36};

__device__ __forceinline__ void gate_write(float* fo, const float* out0,
                                           const float* acc)
{
#pragma unroll
    for (int o=0;o<4;o++) fo[o] = fmaxf(out0[o], 0.f);
    float g[12];
#pragma unroll
    for (int j=0;j<12;j++) g[j] = 1.f/(1.f + expf(-out0[4+j]));
#pragma unroll
    for (int l=0;l<3;l++)
#pragma unroll
        for (int o=0;o<4;o++)
#pragma unroll
            for (int m=0;m<7;m++)
                if (m < c_ML[l])
                    fo[c_FO[l] + o*c_ML[l] + m] =
                        acc[c_AO[l] + o*c_ML[l] + m] * g[l*4+o];
}

__device__ __forceinline__ float WT(int idx, size_t e) {
    return g_wT[(size_t)idx*NEDGE + e];
}

__global__ void __launch_bounds__(256) conv0_kernel()
{
    int gt = blockIdx.x*blockDim.x + threadIdx.x;
    int atom = gt >> 4, sub = gt & 15;
    size_t e = (size_t)atom*KNBR + sub;
    const float* Yp = g_Y + e*16;
    float Y[15];
#pragma unroll
    for (int m=0;m<15;m++) Y[m] = Yp[m];
    float out0[16];
#pragma unroll
    for (int o=0;o<16;o++) out0[o] = red16(WT(o,e)*0.5f);
    float acc[60];
#pragma unroll
    for (int l=0;l<3;l++)
#pragma unroll
        for (int o=0;o<4;o++) {
            float s = WT(16 + l*4 + o, e)*0.5f;
#pragma unroll
            for (int m=0;m<7;m++)
                if (m < c_ML[l])
                    acc[c_AO[l]+o*c_ML[l]+m] = red16(s*Y[c_YO[l]+m]);
        }
    if (sub == 0) gate_write(g_featA + (size_t)atom*64, out0, acc);
}

__global__ void __launch_bounds__(256) conv12_kernel(const int* __restrict__ nbr, int dir)
{
    const float* fin = dir ? g_featB : g_featA;
    float* fout      = dir ? g_featA : g_featB;
    int gt = blockIdx.x*blockDim.x + threadIdx.x;
    int atom = gt >> 4, sub = gt & 15;
    size_t e = (size_t)atom*KNBR + sub;
    int nb = nbr[e];
    const float* Yp = g_Y + e*16;
    const float* fj = fin + (size_t)nb*64;
    float Y[15];
#pragma unroll
    for (int m=0;m<15;m++) Y[m] = Yp[m];
    float f0[4];
#pragma unroll
    for (int i=0;i<4;i++) f0[i] = 0.5f*fj[i];
    float out0[16];
#pragma unroll
    for (int o=0;o<16;o++)
        out0[o] = red16(WT(o*4,e)*f0[0] + WT(o*4+1,e)*f0[1] +
                        WT(o*4+2,e)*f0[2] + WT(o*4+3,e)*f0[3]);
    float acc[60];
#pragma unroll
    for (int l=0;l<3;l++) {
        float fl[28];
#pragma unroll
        for (int q=0;q<28;q++)
            if (q < 4*c_ML[l]) fl[q] = 0.5f*fj[c_FO[l]+q];
#pragma unroll
        for (int o=0;o<4;o++) {
            int wb = 64 + l*32 + o*4;
            float s = WT(wb,e)*f0[0]+WT(wb+1,e)*f0[1]+WT(wb+2,e)*f0[2]+WT(wb+3,e)*f0[3];
            float wA[4];
#pragma unroll
            for (int i=0;i<4;i++) wA[i] = WT(wb+16+i, e);
#pragma unroll
            for (int m=0;m<7;m++)
                if (m < c_ML[l]) {
                    float v = s*Y[c_YO[l]+m];
#pragma unroll
                    for (int i=0;i<4;i++) v += wA[i]*fl[i*c_ML[l]+m];
                    acc[c_AO[l]+o*c_ML[l]+m] = red16(v);
                }
        }
    }
    if (sub == 0) gate_write(fout + (size_t)atom*64, out0, acc);
}

__global__ void __launch_bounds__(256) conv3_kernel(const int* __restrict__ nbr)
{
    int gt = blockIdx.x*blockDim.x + threadIdx.x;
    int atom = gt >> 4, sub = gt & 15;
    size_t e = (size_t)atom*KNBR + sub;
    int nb = nbr[e];
    const float* fj = g_featA + (size_t)nb*64;
    float f0[4];
#pragma unroll
    for (int i=0;i<4;i++) f0[i] = 0.5f*fj[i];
#pragma unroll
    for (int o=0;o<64;o++) {
        float v = WT(o*4,e)*f0[0] + WT(o*4+1,e)*f0[1] +
                  WT(o*4+2,e)*f0[2] + WT(o*4+3,e)*f0[3];
        v = red16(v);
        if (sub == 0) g_featB[(size_t)atom*64 + o] = fmaxf(v, 0.f);
    }
}

__global__ void pool1_kernel()
{
    __shared__ float sm[256];
    int b = blockIdx.x, tid = threadIdx.x, t = tid >> 6, f = tid & 63;
    float s = 0.f;
    for (int a = b*512 + t; a < (b+1)*512; a += 4)
        s += g_featB[(size_t)a*64 + f];
    sm[tid] = s;
    __syncthreads();
    if (t == 0) g_part[b*64+f] = sm[f] + sm[64+f] + sm[128+f] + sm[192+f];
}
__global__ void pool2_kernel(const float* __restrict__ lw,
                             const float* __restrict__ lb, float* out)
{
    __shared__ float pooled[64];
    int tid = threadIdx.x;
    if (tid < 64) {
        float s = 0.f;
        for (int b=0;b<64;b++) s += g_part[b*64+tid];
        pooled[tid] = s*(1.f/32768.f);
    }
    __syncthreads();
    if (tid < 10) {
        float s = lb[tid];
        for (int f=0;f<64;f++) s += pooled[f]*lw[f*10+tid];
        out[tid] = s;
    }
}

extern "C" void kernel_launch(void* const* d_in, const int* in_sizes, int n_in,
                              void* d_out, int out_size)
{
    const float *coords=0,*shift=0,*lw=0,*lb=0;
    const float *w1[4]={0,0,0,0}, *w2[4]={0,0,0,0}, *w3[4]={0,0,0,0};
    const int* nbr=0;
    int n1=0, n2=0, n3m=0;
    for (int i=0;i<n_in;i++) {
        switch (in_sizes[i]) {
            case 98304:   coords = (const float*)d_in[i]; break;
            case 1572864: shift  = (const float*)d_in[i]; break;
            case 524288:  nbr    = (const int*)d_in[i];   break;
            case 1000:    if (n1<4) w1[n1++] = (const float*)d_in[i]; break;
            case 10000:   if (n2<4) w2[n2++] = (const float*)d_in[i]; break;
            case 2800:    w3[0] = (const float*)d_in[i];  break;
            case 16000:   if (n3m<2) w3[1+n3m++] = (const float*)d_in[i]; break;
            case 25600:   w3[3] = (const float*)d_in[i];  break;
            case 640:     lw = (const float*)d_in[i];     break;
            case 10:      lb = (const float*)d_in[i];     break;
            default: break;
        }
    }
    if (!coords || !shift || !nbr || !lw || !lb ||
        !w1[0]||!w1[1]||!w1[2]||!w1[3] || !w2[0]||!w2[1]||!w2[2]||!w2[3] ||
        !w3[0]||!w3[1]||!w3[2]||!w3[3]) {
        pool2_kernel<<<1, 128>>>(lw ? lw : (const float*)d_in[0],
                                 lb ? lb : (const float*)d_in[0], (float*)d_out);
        return;
    }
    float* out = (float*)d_out;

    cudaFuncSetAttribute(radial_kernel<28>,  cudaFuncAttributeMaxDynamicSharedMemorySize, RK<28>::SMEMB);
    cudaFuncSetAttribute(radial_kernel<160>, cudaFuncAttributeMaxDynamicSharedMemorySize, RK<160>::SMEMB);
    cudaFuncSetAttribute(radial_kernel<256>, cudaFuncAttributeMaxDynamicSharedMemorySize, RK<256>::SMEMB);

    geom_kernel<<<NEDGE/256, 256>>>(coords, shift, nbr);
    radial_kernel<28><<<NEDGE/128, 512, RK<28>::SMEMB>>>(w1[0], w2[0], w3[0]);
    conv0_kernel<<<NATOM*16/256, 256>>>();
    radial_kernel<160><<<NEDGE/128, 512, RK<160>::SMEMB>>>(w1[1], w2[1], w3[1]);
    conv12_kernel<<<NATOM*16/256, 256>>>(nbr, 0);
    radial_kernel<160><<<NEDGE/128, 512, RK<160>::SMEMB>>>(w1[2], w2[2], w3[2]);
    conv12_kernel<<<NATOM*16/256, 256>>>(nbr, 1);
    radial_kernel<256><<<NEDGE/128, 512, RK<256>::SMEMB>>>(w1[3], w2[3], w3[3]);
    conv3_kernel<<<NATOM*16/256, 256>>>(nbr);
    pool1_kernel<<<64, 256>>>();
    pool2_kernel<<<1, 128>>>(lw, lb, out);
}

// round 8
// speedup vs baseline: 1.4484x; 1.4484x over previous
#include <cuda_runtime.h>
#include <math.h>
#include <stdint.h>

#define NATOM 32768
#define KNBR 16
#define NEDGE (NATOM*KNBR)

__device__ __align__(16) float g_basisT[(size_t)10*NEDGE];   // [b][e]
__device__ __align__(16) float g_Y[(size_t)NEDGE*16];
__device__ __align__(16) float g_wT[(size_t)256*NEDGE];      // [j][e] per layer
__device__ __align__(16) float g_featA[(size_t)NATOM*64];
__device__ __align__(16) float g_featB[(size_t)NATOM*64];
__device__ float g_part[64*64];

__device__ __forceinline__ float tf32r(float x) {
    uint32_t u; asm("cvt.rna.tf32.f32 %0, %1;" : "=r"(u) : "f"(x));
    return __uint_as_float(u);
}
__device__ __forceinline__ void mma8(float4& d, uint32_t a0, uint32_t a1,
                                     uint32_t a2, uint32_t a3,
                                     uint32_t b0, uint32_t b1) {
    asm volatile(
        "mma.sync.aligned.m16n8k8.row.col.f32.tf32.tf32.f32 "
        "{%0,%1,%2,%3},{%4,%5,%6,%7},{%8,%9},{%0,%1,%2,%3};"
        : "+f"(d.x), "+f"(d.y), "+f"(d.z), "+f"(d.w)
        : "r"(a0), "r"(a1), "r"(a2), "r"(a3), "r"(b0), "r"(b1));
}

__global__ void geom_kernel(const float* __restrict__ coords,
                            const float* __restrict__ shift,
                            const int*   __restrict__ nbr)
{
    int e = blockIdx.x*blockDim.x + threadIdx.x;
    if (e >= NEDGE) return;
    int n  = e >> 4;
    int nb = nbr[e];
    float x = coords[3*nb+0] + shift[3*(size_t)e+0] - coords[3*n+0];
    float y = coords[3*nb+1] + shift[3*(size_t)e+1] - coords[3*n+1];
    float z = coords[3*nb+2] + shift[3*(size_t)e+2] - coords[3*n+2];
    float r  = sqrtf(x*x + y*y + z*z);
    float inv = 1.0f/fmaxf(r, 1e-6f);
    float dx = x*inv, dy = y*inv, dz = z*inv;
    float x2 = dx*dx, y2 = dy*dy, z2 = dz*dz;
    float Y[16];
    Y[0]=0.4886025f*dy; Y[1]=0.4886025f*dz; Y[2]=0.4886025f*dx;
    Y[3]=1.0925484f*dx*dy; Y[4]=1.0925484f*dy*dz; Y[5]=0.3153916f*(3.f*z2-1.f);
    Y[6]=1.0925484f*dx*dz; Y[7]=0.5462742f*(x2-y2);
    Y[8]=0.5900436f*dy*(3.f*x2-y2); Y[9]=2.8906114f*dx*dy*dz;
    Y[10]=0.4570458f*dy*(5.f*z2-1.f); Y[11]=0.3731763f*dz*(5.f*z2-3.f);
    Y[12]=0.4570458f*dx*(5.f*z2-1.f); Y[13]=1.4453057f*(x2-y2)*dz;
    Y[14]=0.5900436f*dx*(x2-3.f*y2); Y[15]=0.f;
    float* Yp = g_Y + (size_t)e*16;
#pragma unroll
    for (int q=0;q<4;q++)
        *(float4*)(Yp+4*q) = make_float4(Y[4*q],Y[4*q+1],Y[4*q+2],Y[4*q+3]);
    float mask = (r < 2.0f && r > 1e-6f) ? 1.f : 0.f;
    const float step = 2.0f/9.0f, invstep = 4.5f;
#pragma unroll
    for (int b=0;b<10;b++) {
        float xr = (r - (float)b*step)*invstep;
        float v = 0.f;
        if (fabsf(xr) < 1.0f) { float c = cospif(0.5f*xr); v = c*c; }
        g_basisT[(size_t)b*NEDGE + e] = v*mask;
    }
}

// K padded to 104 (13 k-steps of 8); h1/h2 rows [k][132] (132 breaks bank conflicts)
template<int NW> struct RK {
    static constexpr int NP     = (NW + 7) & ~7;          // 32,160,256
    static constexpr int NTILES = NP/8;
    static constexpr int SPLIT  = (NTILES + 1)/2;
    static constexpr int NTW    = SPLIT;                  // max n-tiles per warp
    static constexpr int WBF    = (104*NP > 10816) ? 104*NP : 10816;
    static constexpr int OFF_H1 = 1000 + WBF;
    static constexpr int OFF_H2 = OFF_H1 + 13728;         // 104*132
    static constexpr int SMEMB  = (OFF_H2 + 13728)*4;
};

template<int NW>
__global__ void __launch_bounds__(512) radial_kernel(
    const float* __restrict__ W1, const float* __restrict__ W2,
    const float* __restrict__ W3)
{
    extern __shared__ float sm[];
    float* s_w1 = sm;                       // [10][100] fp32
    float* s_wB = sm + 1000;                // W2 [104][104] then W3 [104][NP], tf32
    float* s_h1 = sm + RK<NW>::OFF_H1;      // [k][e] 104x132, tf32
    float* s_h2 = sm + RK<NW>::OFF_H2;      // [j][e] 104x132, tf32 (head reused for basis)
    float* s_bT = s_h2;                     // [b][e] 10x128
    const int tid  = threadIdx.x;
    const int warp = tid >> 5, lane = tid & 31;
    const int g = lane >> 2, t = lane & 3;
    const size_t ebase = (size_t)blockIdx.x*128;

    for (int i = tid; i < 1000; i += 512) s_w1[i] = W1[i];
    for (int i = tid; i < 1280; i += 512) {
        int b = i >> 7, e = i & 127;
        s_bT[b*128 + e] = g_basisT[(size_t)b*NEDGE + ebase + e];
    }
    // stage W2 padded [104][104], tf32-rounded
    for (int i = tid; i < 10816; i += 512) {
        int k = i/104, j = i%104;
        s_wB[i] = (k < 100 && j < 100) ? tf32r(W2[k*100 + j]) : 0.f;
    }
    // zero h1 k-pad rows 100..103
    for (int i = tid; i < 4*132; i += 512) s_h1[100*132 + i] = 0.f;
    __syncthreads();

    // phase A (scalar): h1[k][e] = tf32(relu(basis @ W1))
    for (int iq = tid; iq < 3200; iq += 512) {
        int k = iq >> 5, c0 = (iq & 31)*4;
        float ax=0.f, ay=0.f, az=0.f, aw=0.f;
#pragma unroll
        for (int b = 0; b < 10; b++) {
            float4 bv = *(const float4*)&s_bT[b*128 + c0];
            float w = s_w1[b*100 + k];
            ax += bv.x*w; ay += bv.y*w; az += bv.z*w; aw += bv.w*w;
        }
        *(float4*)&s_h1[k*132 + c0] =
            make_float4(tf32r(fmaxf(ax,0.f)), tf32r(fmaxf(ay,0.f)),
                        tf32r(fmaxf(az,0.f)), tf32r(fmaxf(aw,0.f)));
    }
    __syncthreads();

    // phase B (mma): h2[j][e] = tf32(relu(h1^T @ W2)), 13 n-tiles over j=0..103
    {
        const int m = warp & 7, half = warp >> 3;
        const int nbeg = half ? 7 : 0, ncnt = half ? 6 : 7;
        const int arow = m*16 + g;
        float4 acc[7];
#pragma unroll
        for (int nt=0;nt<7;nt++) acc[nt] = make_float4(0.f,0.f,0.f,0.f);
        for (int ks = 0; ks < 13; ks++) {
            const int kb = ks*8;
            uint32_t a0 = __float_as_uint(s_h1[(kb+t  )*132 + arow]);
            uint32_t a1 = __float_as_uint(s_h1[(kb+t  )*132 + arow + 8]);
            uint32_t a2 = __float_as_uint(s_h1[(kb+t+4)*132 + arow]);
            uint32_t a3 = __float_as_uint(s_h1[(kb+t+4)*132 + arow + 8]);
#pragma unroll
            for (int nt=0;nt<7;nt++) {
                if (nt < ncnt) {
                    int nb = (nbeg+nt)*8;
                    uint32_t b0 = __float_as_uint(s_wB[(kb+t  )*104 + nb + g]);
                    uint32_t b1 = __float_as_uint(s_wB[(kb+t+4)*104 + nb + g]);
                    mma8(acc[nt], a0,a1,a2,a3, b0,b1);
                }
            }
        }
#pragma unroll
        for (int nt=0;nt<7;nt++)
            if (nt < ncnt) {
                int col = (nbeg+nt)*8 + 2*t;
                int row = m*16 + g;
                s_h2[ col   *132 + row    ] = tf32r(fmaxf(acc[nt].x,0.f));
                s_h2[(col+1)*132 + row    ] = tf32r(fmaxf(acc[nt].y,0.f));
                s_h2[ col   *132 + row + 8] = tf32r(fmaxf(acc[nt].z,0.f));
                s_h2[(col+1)*132 + row + 8] = tf32r(fmaxf(acc[nt].w,0.f));
            }
    }
    __syncthreads();
    // stage W3 padded [104][NP], tf32-rounded (overwrites W2)
    for (int i = tid; i < 104*RK<NW>::NP; i += 512) {
        int k = i/RK<NW>::NP, j = i%RK<NW>::NP;
        s_wB[i] = (k < 100 && j < NW) ? tf32r(W3[k*NW + j]) : 0.f;
    }
    __syncthreads();

    // phase C (mma): out[j][e] = h2^T @ W3 -> g_wT (fp32)
    {
        constexpr int NP = RK<NW>::NP;
        constexpr int NTILES = RK<NW>::NTILES;
        constexpr int SPLIT = RK<NW>::SPLIT;
        constexpr int NTW = RK<NW>::NTW;
        const int m = warp & 7, half = warp >> 3;
        const int nbeg = half ? SPLIT : 0;
        const int ncnt = half ? (NTILES - SPLIT) : SPLIT;
        const int arow = m*16 + g;
        float4 acc[NTW];
#pragma unroll
        for (int nt=0;nt<NTW;nt++) acc[nt] = make_float4(0.f,0.f,0.f,0.f);
        for (int ks = 0; ks < 13; ks++) {
            const int kb = ks*8;
            uint32_t a0 = __float_as_uint(s_h2[(kb+t  )*132 + arow]);
            uint32_t a1 = __float_as_uint(s_h2[(kb+t  )*132 + arow + 8]);
            uint32_t a2 = __float_as_uint(s_h2[(kb+t+4)*132 + arow]);
            uint32_t a3 = __float_as_uint(s_h2[(kb+t+4)*132 + arow + 8]);
#pragma unroll
            for (int nt=0;nt<NTW;nt++) {
                if (nt < ncnt) {
                    int nb = (nbeg+nt)*8;
                    uint32_t b0 = __float_as_uint(s_wB[(kb+t  )*NP + nb + g]);
                    uint32_t b1 = __float_as_uint(s_wB[(kb+t+4)*NP + nb + g]);
                    mma8(acc[nt], a0,a1,a2,a3, b0,b1);
                }
            }
        }
        const size_t eg = ebase + m*16 + g;
#pragma unroll
        for (int nt=0;nt<NTW;nt++)
            if (nt < ncnt) {
                int j0 = (nbeg+nt)*8 + 2*t;
                if (j0 < NW) {
                    g_wT[(size_t)j0*NEDGE + eg    ] = acc[nt].x;
                    g_wT[(size_t)j0*NEDGE + eg + 8] = acc[nt].z;
                }
                if (j0+1 < NW) {
                    g_wT[(size_t)(j0+1)*NEDGE + eg    ] = acc[nt].y;
                    g_wT[(size_t)(j0+1)*NEDGE + eg + 8] = acc[nt].w;
                }
            }
    }
}

__device__ __forceinline__ float red16(float v) {
    v += __shfl_xor_sync(0xffffffffu, v, 8);
    v += __shfl_xor_sync(0xffffffffu, v, 4);
    v += __shfl_xor_sync(0xffffffffu, v, 2);
    v += __shfl_xor_sync(0xffffffffu, v, 1);
    return v;
}
__constant__ int c_ML[3] = {3,5,7};
__constant__ int c_AO[3] = {0,12,32};
__constant__ int c_YO[3] = {0,3,8};
__constant__ int c_FO[3] = {4,16,36};

__device__ __forceinline__ void gate_write(float* fo, const float* out0,
                                           const float* acc)
{
#pragma unroll
    for (int o=0;o<4;o++) fo[o] = fmaxf(out0[o], 0.f);
    float g[12];
#pragma unroll
    for (int j=0;j<12;j++) g[j] = 1.f/(1.f + expf(-out0[4+j]));
#pragma unroll
    for (int l=0;l<3;l++)
#pragma unroll
        for (int o=0;o<4;o++)
#pragma unroll
            for (int m=0;m<7;m++)
                if (m < c_ML[l])
                    fo[c_FO[l] + o*c_ML[l] + m] =
                        acc[c_AO[l] + o*c_ML[l] + m] * g[l*4+o];
}

__device__ __forceinline__ float WT(int idx, size_t e) {
    return g_wT[(size_t)idx*NEDGE + e];
}

__global__ void __launch_bounds__(256) conv0_kernel()
{
    int gt = blockIdx.x*blockDim.x + threadIdx.x;
    int atom = gt >> 4, sub = gt & 15;
    size_t e = (size_t)atom*KNBR + sub;
    const float* Yp = g_Y + e*16;
    float Y[15];
#pragma unroll
    for (int m=0;m<15;m++) Y[m] = Yp[m];
    float out0[16];
#pragma unroll
    for (int o=0;o<16;o++) out0[o] = red16(WT(o,e)*0.5f);
    float acc[60];
#pragma unroll
    for (int l=0;l<3;l++)
#pragma unroll
        for (int o=0;o<4;o++) {
            float s = WT(16 + l*4 + o, e)*0.5f;
#pragma unroll
            for (int m=0;m<7;m++)
                if (m < c_ML[l])
                    acc[c_AO[l]+o*c_ML[l]+m] = red16(s*Y[c_YO[l]+m]);
        }
    if (sub == 0) gate_write(g_featA + (size_t)atom*64, out0, acc);
}

__global__ void __launch_bounds__(256) conv12_kernel(const int* __restrict__ nbr, int dir)
{
    const float* fin = dir ? g_featB : g_featA;
    float* fout      = dir ? g_featA : g_featB;
    int gt = blockIdx.x*blockDim.x + threadIdx.x;
    int atom = gt >> 4, sub = gt & 15;
    size_t e = (size_t)atom*KNBR + sub;
    int nb = nbr[e];
    const float* Yp = g_Y + e*16;
    const float* fj = fin + (size_t)nb*64;
    float Y[15];
#pragma unroll
    for (int m=0;m<15;m++) Y[m] = Yp[m];
    float f0[4];
#pragma unroll
    for (int i=0;i<4;i++) f0[i] = 0.5f*fj[i];
    float out0[16];
#pragma unroll
    for (int o=0;o<16;o++)
        out0[o] = red16(WT(o*4,e)*f0[0] + WT(o*4+1,e)*f0[1] +
                        WT(o*4+2,e)*f0[2] + WT(o*4+3,e)*f0[3]);
    float acc[60];
#pragma unroll
    for (int l=0;l<3;l++) {
        float fl[28];
#pragma unroll
        for (int q=0;q<28;q++)
            if (q < 4*c_ML[l]) fl[q] = 0.5f*fj[c_FO[l]+q];
#pragma unroll
        for (int o=0;o<4;o++) {
            int wb = 64 + l*32 + o*4;
            float s = WT(wb,e)*f0[0]+WT(wb+1,e)*f0[1]+WT(wb+2,e)*f0[2]+WT(wb+3,e)*f0[3];
            float wA[4];
#pragma unroll
            for (int i=0;i<4;i++) wA[i] = WT(wb+16+i, e);
#pragma unroll
            for (int m=0;m<7;m++)
                if (m < c_ML[l]) {
                    float v = s*Y[c_YO[l]+m];
#pragma unroll
                    for (int i=0;i<4;i++) v += wA[i]*fl[i*c_ML[l]+m];
                    acc[c_AO[l]+o*c_ML[l]+m] = red16(v);
                }
        }
    }
    if (sub == 0) gate_write(fout + (size_t)atom*64, out0, acc);
}

__global__ void __launch_bounds__(256) conv3_kernel(const int* __restrict__ nbr)
{
    int gt = blockIdx.x*blockDim.x + threadIdx.x;
    int atom = gt >> 4, sub = gt & 15;
    size_t e = (size_t)atom*KNBR + sub;
    int nb = nbr[e];
    const float* fj = g_featA + (size_t)nb*64;
    float f0[4];
#pragma unroll
    for (int i=0;i<4;i++) f0[i] = 0.5f*fj[i];
#pragma unroll
    for (int o=0;o<64;o++) {
        float v = WT(o*4,e)*f0[0] + WT(o*4+1,e)*f0[1] +
                  WT(o*4+2,e)*f0[2] + WT(o*4+3,e)*f0[3];
        v = red16(v);
        if (sub == 0) g_featB[(size_t)atom*64 + o] = fmaxf(v, 0.f);
    }
}

__global__ void pool1_kernel()
{
    __shared__ float sm[256];
    int b = blockIdx.x, tid = threadIdx.x, t = tid >> 6, f = tid & 63;
    float s = 0.f;
    for (int a = b*512 + t; a < (b+1)*512; a += 4)
        s += g_featB[(size_t)a*64 + f];
    sm[tid] = s;
    __syncthreads();
    if (t == 0) g_part[b*64+f] = sm[f] + sm[64+f] + sm[128+f] + sm[192+f];
}
__global__ void pool2_kernel(const float* __restrict__ lw,
                             const float* __restrict__ lb, float* out)
{
    __shared__ float pooled[64];
    int tid = threadIdx.x;
    if (tid < 64) {
        float s = 0.f;
        for (int b=0;b<64;b++) s += g_part[b*64+tid];
        pooled[tid] = s*(1.f/32768.f);
    }
    __syncthreads();
    if (tid < 10) {
        float s = lb[tid];
        for (int f=0;f<64;f++) s += pooled[f]*lw[f*10+tid];
        out[tid] = s;
    }
}

extern "C" void kernel_launch(void* const* d_in, const int* in_sizes, int n_in,
                              void* d_out, int out_size)
{
    const float *coords=0,*shift=0,*lw=0,*lb=0;
    const float *w1[4]={0,0,0,0}, *w2[4]={0,0,0,0}, *w3[4]={0,0,0,0};
    const int* nbr=0;
    int n1=0, n2=0, n3m=0;
    for (int i=0;i<n_in;i++) {
        switch (in_sizes[i]) {
            case 98304:   coords = (const float*)d_in[i]; break;
            case 1572864: shift  = (const float*)d_in[i]; break;
            case 524288:  nbr    = (const int*)d_in[i];   break;
            case 1000:    if (n1<4) w1[n1++] = (const float*)d_in[i]; break;
            case 10000:   if (n2<4) w2[n2++] = (const float*)d_in[i]; break;
            case 2800:    w3[0] = (const float*)d_in[i];  break;
            case 16000:   if (n3m<2) w3[1+n3m++] = (const float*)d_in[i]; break;
            case 25600:   w3[3] = (const float*)d_in[i];  break;
            case 640:     lw = (const float*)d_in[i];     break;
            case 10:      lb = (const float*)d_in[i];     break;
            default: break;
        }
    }
    if (!coords || !shift || !nbr || !lw || !lb ||
        !w1[0]||!w1[1]||!w1[2]||!w1[3] || !w2[0]||!w2[1]||!w2[2]||!w2[3] ||
        !w3[0]||!w3[1]||!w3[2]||!w3[3]) {
        pool2_kernel<<<1, 128>>>(lw ? lw : (const float*)d_in[0],
                                 lb ? lb : (const float*)d_in[0], (float*)d_out);
        return;
    }
    float* out = (float*)d_out;

    cudaFuncSetAttribute(radial_kernel<28>,  cudaFuncAttributeMaxDynamicSharedMemorySize, RK<28>::SMEMB);
    cudaFuncSetAttribute(radial_kernel<160>, cudaFuncAttributeMaxDynamicSharedMemorySize, RK<160>::SMEMB);
    cudaFuncSetAttribute(radial_kernel<256>, cudaFuncAttributeMaxDynamicSharedMemorySize, RK<256>::SMEMB);

    geom_kernel<<<NEDGE/256, 256>>>(coords, shift, nbr);
    radial_kernel<28><<<NEDGE/128, 512, RK<28>::SMEMB>>>(w1[0], w2[0], w3[0]);
    conv0_kernel<<<NATOM*16/256, 256>>>();
    radial_kernel<160><<<NEDGE/128, 512, RK<160>::SMEMB>>>(w1[1], w2[1], w3[1]);
    conv12_kernel<<<NATOM*16/256, 256>>>(nbr, 0);
    radial_kernel<160><<<NEDGE/128, 512, RK<160>::SMEMB>>>(w1[2], w2[2], w3[2]);
    conv12_kernel<<<NATOM*16/256, 256>>>(nbr, 1);
    radial_kernel<256><<<NEDGE/128, 512, RK<256>::SMEMB>>>(w1[3], w2[3], w3[3]);
    conv3_kernel<<<NATOM*16/256, 256>>>(nbr);
    pool1_kernel<<<64, 256>>>();
    pool2_kernel<<<1, 128>>>(lw, lb, out);
}

// round 9
// speedup vs baseline: 1.7970x; 1.2406x over previous
#include <cuda_runtime.h>
#include <math.h>
#include <stdint.h>

#define NATOM 32768
#define KNBR 16
#define NEDGE (NATOM*KNBR)

__device__ __align__(16) float g_basisT[(size_t)10*NEDGE];   // [b][e]
__device__ __align__(16) float g_Y[(size_t)NEDGE*16];
__device__ __align__(16) float g_wT[(size_t)256*NEDGE];      // [j][e] per layer
__device__ __align__(16) float g_featA[(size_t)NATOM*64];
__device__ __align__(16) float g_featB[(size_t)NATOM*64];
__device__ float g_part[64*64];

__device__ __forceinline__ float tf32r(float x) {
    uint32_t u; asm("cvt.rna.tf32.f32 %0, %1;" : "=r"(u) : "f"(x));
    return __uint_as_float(u);
}
__device__ __forceinline__ void mma8(float4& d, uint32_t a0, uint32_t a1,
                                     uint32_t a2, uint32_t a3,
                                     uint32_t b0, uint32_t b1) {
    asm volatile(
        "mma.sync.aligned.m16n8k8.row.col.f32.tf32.tf32.f32 "
        "{%0,%1,%2,%3},{%4,%5,%6,%7},{%8,%9},{%0,%1,%2,%3};"
        : "+f"(d.x), "+f"(d.y), "+f"(d.z), "+f"(d.w)
        : "r"(a0), "r"(a1), "r"(a2), "r"(a3), "r"(b0), "r"(b1));
}

__global__ void geom_kernel(const float* __restrict__ coords,
                            const float* __restrict__ shift,
                            const int*   __restrict__ nbr)
{
    int e = blockIdx.x*blockDim.x + threadIdx.x;
    if (e >= NEDGE) return;
    int n  = e >> 4;
    int nb = nbr[e];
    float x = coords[3*nb+0] + shift[3*(size_t)e+0] - coords[3*n+0];
    float y = coords[3*nb+1] + shift[3*(size_t)e+1] - coords[3*n+1];
    float z = coords[3*nb+2] + shift[3*(size_t)e+2] - coords[3*n+2];
    float r  = sqrtf(x*x + y*y + z*z);
    float inv = 1.0f/fmaxf(r, 1e-6f);
    float dx = x*inv, dy = y*inv, dz = z*inv;
    float x2 = dx*dx, y2 = dy*dy, z2 = dz*dz;
    float Y[16];
    Y[0]=0.4886025f*dy; Y[1]=0.4886025f*dz; Y[2]=0.4886025f*dx;
    Y[3]=1.0925484f*dx*dy; Y[4]=1.0925484f*dy*dz; Y[5]=0.3153916f*(3.f*z2-1.f);
    Y[6]=1.0925484f*dx*dz; Y[7]=0.5462742f*(x2-y2);
    Y[8]=0.5900436f*dy*(3.f*x2-y2); Y[9]=2.8906114f*dx*dy*dz;
    Y[10]=0.4570458f*dy*(5.f*z2-1.f); Y[11]=0.3731763f*dz*(5.f*z2-3.f);
    Y[12]=0.4570458f*dx*(5.f*z2-1.f); Y[13]=1.4453057f*(x2-y2)*dz;
    Y[14]=0.5900436f*dx*(x2-3.f*y2); Y[15]=0.f;
    float* Yp = g_Y + (size_t)e*16;
#pragma unroll
    for (int q=0;q<4;q++)
        *(float4*)(Yp+4*q) = make_float4(Y[4*q],Y[4*q+1],Y[4*q+2],Y[4*q+3]);
    float mask = (r < 2.0f && r > 1e-6f) ? 1.f : 0.f;
    const float step = 2.0f/9.0f, invstep = 4.5f;
#pragma unroll
    for (int b=0;b<10;b++) {
        float xr = (r - (float)b*step)*invstep;
        float v = 0.f;
        if (fabsf(xr) < 1.0f) { float c = cospif(0.5f*xr); v = c*c; }
        g_basisT[(size_t)b*NEDGE + e] = v*mask;
    }
}

// h1/h2 stride 140 (mod32=12 -> conflict-free A-loads & epilogue stores)
// W3 frag stride NPP=NP+8 (mod32=8 -> conflict-free B-loads)
#define HS 140
template<int NW> struct RK {
    static constexpr int NP     = (NW + 7) & ~7;          // 32,160,256
    static constexpr int NPP    = NP + 8;                 // 40,168,264
    static constexpr int NTILES = NP/8;
    static constexpr int SPLIT  = (NTILES + 1)/2;
    static constexpr int NTW    = SPLIT;
    static constexpr int WBF    = (104*NPP > 10816) ? 104*NPP : 10816;
    static constexpr int OFF_H1 = 1000 + WBF;
    static constexpr int OFF_H2 = OFF_H1 + 104*HS;
    static constexpr int SMEMB  = (OFF_H2 + 104*HS)*4;
};

template<int NW>
__global__ void __launch_bounds__(512) radial_kernel(
    const float* __restrict__ W1, const float* __restrict__ W2,
    const float* __restrict__ W3)
{
    extern __shared__ float sm[];
    float* s_w1 = sm;                       // [10][100] fp32
    float* s_wB = sm + 1000;                // W2 [104][104] then W3 [104][NPP], tf32
    float* s_h1 = sm + RK<NW>::OFF_H1;      // [k][e] 104xHS, tf32
    float* s_h2 = sm + RK<NW>::OFF_H2;      // [j][e] 104xHS, tf32 (head reused for basis)
    float* s_bT = s_h2;                     // [b][e] 10x128
    const int tid  = threadIdx.x;
    const int warp = tid >> 5, lane = tid & 31;
    const int g = lane >> 2, t = lane & 3;
    const size_t ebase = (size_t)blockIdx.x*128;

    for (int i = tid; i < 1000; i += 512) s_w1[i] = W1[i];
    for (int i = tid; i < 1280; i += 512) {
        int b = i >> 7, e = i & 127;
        s_bT[b*128 + e] = g_basisT[(size_t)b*NEDGE + ebase + e];
    }
    // stage W2 padded [104][104], tf32-rounded
    for (int i = tid; i < 10816; i += 512) {
        int k = i/104, j = i%104;
        s_wB[i] = (k < 100 && j < 100) ? tf32r(W2[k*100 + j]) : 0.f;
    }
    // zero h1 k-pad rows 100..103
    for (int i = tid; i < 4*HS; i += 512) s_h1[100*HS + i] = 0.f;
    __syncthreads();

    // phase A (scalar): h1[k][e] = tf32(relu(basis @ W1)); 10 k per thread,
    // basis tile loaded once into registers (tid<320: kg=tid>>5, equad=tid&31)
    if (tid < 320) {
        const int kg = tid >> 5, c0 = (tid & 31)*4;
        float4 bv[10];
#pragma unroll
        for (int b=0;b<10;b++) bv[b] = *(const float4*)&s_bT[b*128 + c0];
#pragma unroll
        for (int kk=0;kk<10;kk++) {
            const int k = kg*10 + kk;
            float ax=0.f, ay=0.f, az=0.f, aw=0.f;
#pragma unroll
            for (int b=0;b<10;b++) {
                float w = s_w1[b*100 + k];
                ax += bv[b].x*w; ay += bv[b].y*w;
                az += bv[b].z*w; aw += bv[b].w*w;
            }
            *(float4*)&s_h1[k*HS + c0] =
                make_float4(tf32r(fmaxf(ax,0.f)), tf32r(fmaxf(ay,0.f)),
                            tf32r(fmaxf(az,0.f)), tf32r(fmaxf(aw,0.f)));
        }
    }
    __syncthreads();

    // phase B (mma): h2[j][e] = tf32(relu(h1^T @ W2)), 13 n-tiles over j=0..103
    {
        const int m = warp & 7, half = warp >> 3;
        const int nbeg = half ? 7 : 0, ncnt = half ? 6 : 7;
        const int arow = m*16 + g;
        float4 acc[7];
#pragma unroll
        for (int nt=0;nt<7;nt++) acc[nt] = make_float4(0.f,0.f,0.f,0.f);
        for (int ks = 0; ks < 13; ks++) {
            const int kb = ks*8;
            uint32_t a0 = __float_as_uint(s_h1[(kb+t  )*HS + arow]);
            uint32_t a1 = __float_as_uint(s_h1[(kb+t  )*HS + arow + 8]);
            uint32_t a2 = __float_as_uint(s_h1[(kb+t+4)*HS + arow]);
            uint32_t a3 = __float_as_uint(s_h1[(kb+t+4)*HS + arow + 8]);
#pragma unroll
            for (int nt=0;nt<7;nt++) {
                if (nt < ncnt) {
                    int nb = (nbeg+nt)*8;
                    uint32_t b0 = __float_as_uint(s_wB[(kb+t  )*104 + nb + g]);
                    uint32_t b1 = __float_as_uint(s_wB[(kb+t+4)*104 + nb + g]);
                    mma8(acc[nt], a0,a1,a2,a3, b0,b1);
                }
            }
        }
#pragma unroll
        for (int nt=0;nt<7;nt++)
            if (nt < ncnt) {
                int col = (nbeg+nt)*8 + 2*t;
                int row = m*16 + g;
                s_h2[ col   *HS + row    ] = tf32r(fmaxf(acc[nt].x,0.f));
                s_h2[(col+1)*HS + row    ] = tf32r(fmaxf(acc[nt].y,0.f));
                s_h2[ col   *HS + row + 8] = tf32r(fmaxf(acc[nt].z,0.f));
                s_h2[(col+1)*HS + row + 8] = tf32r(fmaxf(acc[nt].w,0.f));
            }
    }
    __syncthreads();
    // stage W3 padded [104][NPP], tf32-rounded (overwrites W2)
    for (int i = tid; i < 104*RK<NW>::NPP; i += 512) {
        int k = i/RK<NW>::NPP, j = i%RK<NW>::NPP;
        s_wB[i] = (k < 100 && j < NW) ? tf32r(W3[k*NW + j]) : 0.f;
    }
    __syncthreads();

    // phase C (mma): out[j][e] = h2^T @ W3 -> g_wT (fp32)
    {
        constexpr int NPP = RK<NW>::NPP;
        constexpr int NTILES = RK<NW>::NTILES;
        constexpr int SPLIT = RK<NW>::SPLIT;
        constexpr int NTW = RK<NW>::NTW;
        const int m = warp & 7, half = warp >> 3;
        const int nbeg = half ? SPLIT : 0;
        const int ncnt = half ? (NTILES - SPLIT) : SPLIT;
        const int arow = m*16 + g;
        float4 acc[NTW];
#pragma unroll
        for (int nt=0;nt<NTW;nt++) acc[nt] = make_float4(0.f,0.f,0.f,0.f);
        for (int ks = 0; ks < 13; ks++) {
            const int kb = ks*8;
            uint32_t a0 = __float_as_uint(s_h2[(kb+t  )*HS + arow]);
            uint32_t a1 = __float_as_uint(s_h2[(kb+t  )*HS + arow + 8]);
            uint32_t a2 = __float_as_uint(s_h2[(kb+t+4)*HS + arow]);
            uint32_t a3 = __float_as_uint(s_h2[(kb+t+4)*HS + arow + 8]);
#pragma unroll
            for (int nt=0;nt<NTW;nt++) {
                if (nt < ncnt) {
                    int nb = (nbeg+nt)*8;
                    uint32_t b0 = __float_as_uint(s_wB[(kb+t  )*NPP + nb + g]);
                    uint32_t b1 = __float_as_uint(s_wB[(kb+t+4)*NPP + nb + g]);
                    mma8(acc[nt], a0,a1,a2,a3, b0,b1);
                }
            }
        }
        const size_t eg = ebase + m*16 + g;
#pragma unroll
        for (int nt=0;nt<NTW;nt++)
            if (nt < ncnt) {
                int j0 = (nbeg+nt)*8 + 2*t;
                if (j0 < NW) {
                    g_wT[(size_t)j0*NEDGE + eg    ] = acc[nt].x;
                    g_wT[(size_t)j0*NEDGE + eg + 8] = acc[nt].z;
                }
                if (j0+1 < NW) {
                    g_wT[(size_t)(j0+1)*NEDGE + eg    ] = acc[nt].y;
                    g_wT[(size_t)(j0+1)*NEDGE + eg + 8] = acc[nt].w;
                }
            }
    }
}

__device__ __forceinline__ float red16(float v) {
    v += __shfl_xor_sync(0xffffffffu, v, 8);
    v += __shfl_xor_sync(0xffffffffu, v, 4);
    v += __shfl_xor_sync(0xffffffffu, v, 2);
    v += __shfl_xor_sync(0xffffffffu, v, 1);
    return v;
}
__constant__ int c_ML[3] = {3,5,7};
__constant__ int c_AO[3] = {0,12,32};
__constant__ int c_YO[3] = {0,3,8};
__constant__ int c_FO[3] = {4,16,36};

__device__ __forceinline__ void gate_write(float* fo, const float* out0,
                                           const float* acc)
{
#pragma unroll
    for (int o=0;o<4;o++) fo[o] = fmaxf(out0[o], 0.f);
    float g[12];
#pragma unroll
    for (int j=0;j<12;j++) g[j] = 1.f/(1.f + expf(-out0[4+j]));
#pragma unroll
    for (int l=0;l<3;l++)
#pragma unroll
        for (int o=0;o<4;o++)
#pragma unroll
            for (int m=0;m<7;m++)
                if (m < c_ML[l])
                    fo[c_FO[l] + o*c_ML[l] + m] =
                        acc[c_AO[l] + o*c_ML[l] + m] * g[l*4+o];
}

__device__ __forceinline__ float WT(int idx, size_t e) {
    return g_wT[(size_t)idx*NEDGE + e];
}

__global__ void __launch_bounds__(256) conv0_kernel()
{
    int gt = blockIdx.x*blockDim.x + threadIdx.x;
    int atom = gt >> 4, sub = gt & 15;
    size_t e = (size_t)atom*KNBR + sub;
    const float* Yp = g_Y + e*16;
    float Y[15];
#pragma unroll
    for (int m=0;m<15;m++) Y[m] = Yp[m];
    float out0[16];
#pragma unroll
    for (int o=0;o<16;o++) out0[o] = red16(WT(o,e)*0.5f);
    float acc[60];
#pragma unroll
    for (int l=0;l<3;l++)
#pragma unroll
        for (int o=0;o<4;o++) {
            float s = WT(16 + l*4 + o, e)*0.5f;
#pragma unroll
            for (int m=0;m<7;m++)
                if (m < c_ML[l])
                    acc[c_AO[l]+o*c_ML[l]+m] = red16(s*Y[c_YO[l]+m]);
        }
    if (sub == 0) gate_write(g_featA + (size_t)atom*64, out0, acc);
}

__global__ void __launch_bounds__(256) conv12_kernel(const int* __restrict__ nbr, int dir)
{
    const float* fin = dir ? g_featB : g_featA;
    float* fout      = dir ? g_featA : g_featB;
    int gt = blockIdx.x*blockDim.x + threadIdx.x;
    int atom = gt >> 4, sub = gt & 15;
    size_t e = (size_t)atom*KNBR + sub;
    int nb = nbr[e];
    const float* Yp = g_Y + e*16;
    const float* fj = fin + (size_t)nb*64;
    float Y[15];
#pragma unroll
    for (int m=0;m<15;m++) Y[m] = Yp[m];
    float f0[4];
#pragma unroll
    for (int i=0;i<4;i++) f0[i] = 0.5f*fj[i];
    float out0[16];
#pragma unroll
    for (int o=0;o<16;o++)
        out0[o] = red16(WT(o*4,e)*f0[0] + WT(o*4+1,e)*f0[1] +
                        WT(o*4+2,e)*f0[2] + WT(o*4+3,e)*f0[3]);
    float acc[60];
#pragma unroll
    for (int l=0;l<3;l++) {
        float fl[28];
#pragma unroll
        for (int q=0;q<28;q++)
            if (q < 4*c_ML[l]) fl[q] = 0.5f*fj[c_FO[l]+q];
#pragma unroll
        for (int o=0;o<4;o++) {
            int wb = 64 + l*32 + o*4;
            float s = WT(wb,e)*f0[0]+WT(wb+1,e)*f0[1]+WT(wb+2,e)*f0[2]+WT(wb+3,e)*f0[3];
            float wA[4];
#pragma unroll
            for (int i=0;i<4;i++) wA[i] = WT(wb+16+i, e);
#pragma unroll
            for (int m=0;m<7;m++)
                if (m < c_ML[l]) {
                    float v = s*Y[c_YO[l]+m];
#pragma unroll
                    for (int i=0;i<4;i++) v += wA[i]*fl[i*c_ML[l]+m];
                    acc[c_AO[l]+o*c_ML[l]+m] = red16(v);
                }
        }
    }
    if (sub == 0) gate_write(fout + (size_t)atom*64, out0, acc);
}

__global__ void __launch_bounds__(256) conv3_kernel(const int* __restrict__ nbr)
{
    int gt = blockIdx.x*blockDim.x + threadIdx.x;
    int atom = gt >> 4, sub = gt & 15;
    size_t e = (size_t)atom*KNBR + sub;
    int nb = nbr[e];
    const float* fj = g_featA + (size_t)nb*64;
    float f0[4];
#pragma unroll
    for (int i=0;i<4;i++) f0[i] = 0.5f*fj[i];
#pragma unroll
    for (int o=0;o<64;o++) {
        float v = WT(o*4,e)*f0[0] + WT(o*4+1,e)*f0[1] +
                  WT(o*4+2,e)*f0[2] + WT(o*4+3,e)*f0[3];
        v = red16(v);
        if (sub == 0) g_featB[(size_t)atom*64 + o] = fmaxf(v, 0.f);
    }
}

__global__ void pool1_kernel()
{
    __shared__ float sm[256];
    int b = blockIdx.x, tid = threadIdx.x, t = tid >> 6, f = tid & 63;
    float s = 0.f;
    for (int a = b*512 + t; a < (b+1)*512; a += 4)
        s += g_featB[(size_t)a*64 + f];
    sm[tid] = s;
    __syncthreads();
    if (t == 0) g_part[b*64+f] = sm[f] + sm[64+f] + sm[128+f] + sm[192+f];
}
__global__ void pool2_kernel(const float* __restrict__ lw,
                             const float* __restrict__ lb, float* out)
{
    __shared__ float pooled[64];
    int tid = threadIdx.x;
    if (tid < 64) {
        float s = 0.f;
        for (int b=0;b<64;b++) s += g_part[b*64+tid];
        pooled[tid] = s*(1.f/32768.f);
    }
    __syncthreads();
    if (tid < 10) {
        float s = lb[tid];
        for (int f=0;f<64;f++) s += pooled[f]*lw[f*10+tid];
        out[tid] = s;
    }
}

extern "C" void kernel_launch(void* const* d_in, const int* in_sizes, int n_in,
                              void* d_out, int out_size)
{
    const float *coords=0,*shift=0,*lw=0,*lb=0;
    const float *w1[4]={0,0,0,0}, *w2[4]={0,0,0,0}, *w3[4]={0,0,0,0};
    const int* nbr=0;
    int n1=0, n2=0, n3m=0;
    for (int i=0;i<n_in;i++) {
        switch (in_sizes[i]) {
            case 98304:   coords = (const float*)d_in[i]; break;
            case 1572864: shift  = (const float*)d_in[i]; break;
            case 524288:  nbr    = (const int*)d_in[i];   break;
            case 1000:    if (n1<4) w1[n1++] = (const float*)d_in[i]; break;
            case 10000:   if (n2<4) w2[n2++] = (const float*)d_in[i]; break;
            case 2800:    w3[0] = (const float*)d_in[i];  break;
            case 16000:   if (n3m<2) w3[1+n3m++] = (const float*)d_in[i]; break;
            case 25600:   w3[3] = (const float*)d_in[i];  break;
            case 640:     lw = (const float*)d_in[i];     break;
            case 10:      lb = (const float*)d_in[i];     break;
            default: break;
        }
    }
    if (!coords || !shift || !nbr || !lw || !lb ||
        !w1[0]||!w1[1]||!w1[2]||!w1[3] || !w2[0]||!w2[1]||!w2[2]||!w2[3] ||
        !w3[0]||!w3[1]||!w3[2]||!w3[3]) {
        pool2_kernel<<<1, 128>>>(lw ? lw : (const float*)d_in[0],
                                 lb ? lb : (const float*)d_in[0], (float*)d_out);
        return;
    }
    float* out = (float*)d_out;

    cudaFuncSetAttribute(radial_kernel<28>,  cudaFuncAttributeMaxDynamicSharedMemorySize, RK<28>::SMEMB);
    cudaFuncSetAttribute(radial_kernel<160>, cudaFuncAttributeMaxDynamicSharedMemorySize, RK<160>::SMEMB);
    cudaFuncSetAttribute(radial_kernel<256>, cudaFuncAttributeMaxDynamicSharedMemorySize, RK<256>::SMEMB);

    geom_kernel<<<NEDGE/256, 256>>>(coords, shift, nbr);
    radial_kernel<28><<<NEDGE/128, 512, RK<28>::SMEMB>>>(w1[0], w2[0], w3[0]);
    conv0_kernel<<<NATOM*16/256, 256>>>();
    radial_kernel<160><<<NEDGE/128, 512, RK<160>::SMEMB>>>(w1[1], w2[1], w3[1]);
    conv12_kernel<<<NATOM*16/256, 256>>>(nbr, 0);
    radial_kernel<160><<<NEDGE/128, 512, RK<160>::SMEMB>>>(w1[2], w2[2], w3[2]);
    conv12_kernel<<<NATOM*16/256, 256>>>(nbr, 1);
    radial_kernel<256><<<NEDGE/128, 512, RK<256>::SMEMB>>>(w1[3], w2[3], w3[3]);
    conv3_kernel<<<NATOM*16/256, 256>>>(nbr);
    pool1_kernel<<<64, 256>>>();
    pool2_kernel<<<1, 128>>>(lw, lb, out);
}